// round 14
// baseline (speedup 1.0000x reference)
#include <cuda_runtime.h>
#include <cuda_bf16.h>
#include <mma.h>
#include <math.h>
#include <type_traits>

using namespace nvcuda;
typedef __nv_bfloat16 bf16;

// ---------------- problem constants ----------------
#define Dm   896
#define Hh   8
#define HDd  112
#define Pp   196
#define Ff   32
#define LQ   1568           // M * P
#define LK   6272           // F * P
#define D4   3584           // 4 * D

// ---------------- scratch (device globals; no allocs allowed) ----------------
__device__ __align__(256) float g_S  [(size_t)Hh * LQ * LK];   // fp32 scores (314 MB)
__device__ __align__(256) bf16  g_Ph [(size_t)Hh * LQ * LK];   // probs hi
__device__ __align__(256) bf16  g_Pl [(size_t)Hh * LQ * LK];   // probs lo

__device__ __align__(256) bf16 g_memh[LQ * Dm], g_meml[LQ * Dm];
__device__ __align__(256) bf16 g_imgh[LK * Dm], g_imgl[LK * Dm];
__device__ __align__(256) bf16 g_qWh[Dm * Dm], g_qWl[Dm * Dm];
__device__ __align__(256) bf16 g_kWh[Dm * Dm], g_kWl[Dm * Dm];
__device__ __align__(256) bf16 g_vWh[Dm * Dm], g_vWl[Dm * Dm];
__device__ __align__(256) bf16 g_oWh[Dm * Dm], g_oWl[Dm * Dm];
__device__ __align__(256) bf16 g_mWh[(size_t)Dm * D4], g_mWl[(size_t)Dm * D4];
__device__ __align__(256) bf16 g_pWh[(size_t)D4 * Dm], g_pWl[(size_t)D4 * Dm];

__device__ __align__(256) bf16 g_Qh[LQ * Dm], g_Ql[LQ * Dm];
__device__ __align__(256) bf16 g_Kh[LK * Dm], g_Kl[LK * Dm];
__device__ __align__(256) bf16 g_Vh[LK * Dm], g_Vl[LK * Dm];
__device__ __align__(256) float g_CTX[LQ * Dm];
__device__ __align__(256) bf16 g_CTXh[LQ * Dm], g_CTXl[LQ * Dm];
__device__ __align__(256) float g_T1[LQ * Dm];
__device__ __align__(256) float g_AO[LQ * Dm];
__device__ __align__(256) bf16 g_AOh[LQ * Dm], g_AOl[LQ * Dm];
__device__ __align__(256) bf16 g_HIDh[(size_t)LQ * D4], g_HIDl[(size_t)LQ * D4];
__device__ __align__(256) float g_T2[LQ * Dm];
__device__ __align__(256) float g_ASUM[LK];

// ---------------- reductions ----------------
__device__ __forceinline__ float warp_reduce_sum(float v) {
#pragma unroll
    for (int o = 16; o > 0; o >>= 1) v += __shfl_down_sync(0xffffffffu, v, o);
    return v;
}
__device__ __forceinline__ float warp_reduce_max(float v) {
#pragma unroll
    for (int o = 16; o > 0; o >>= 1) v = fmaxf(v, __shfl_down_sync(0xffffffffu, v, o));
    return v;
}
__device__ __forceinline__ float block_reduce_sum(float v, float* sred) {
    __syncthreads();
    v = warp_reduce_sum(v);
    if ((threadIdx.x & 31) == 0) sred[threadIdx.x >> 5] = v;
    __syncthreads();
    int nw = (blockDim.x + 31) >> 5;
    if (threadIdx.x < 32) {
        float x = (threadIdx.x < nw) ? sred[threadIdx.x] : 0.f;
        x = warp_reduce_sum(x);
        if (threadIdx.x == 0) sred[0] = x;
    }
    __syncthreads();
    return sred[0];
}
__device__ __forceinline__ float block_reduce_max(float v, float* sred) {
    __syncthreads();
    v = warp_reduce_max(v);
    if ((threadIdx.x & 31) == 0) sred[threadIdx.x >> 5] = v;
    __syncthreads();
    int nw = (blockDim.x + 31) >> 5;
    if (threadIdx.x < 32) {
        float x = (threadIdx.x < nw) ? sred[threadIdx.x] : -1e30f;
        x = warp_reduce_max(x);
        if (threadIdx.x == 0) sred[0] = x;
    }
    __syncthreads();
    return sred[0];
}

// ---------------- utility kernels ----------------
__global__ void zero_kernel(float* __restrict__ p, int n) {
    int i = blockIdx.x * blockDim.x + threadIdx.x;
    if (i < n) p[i] = 0.f;
}

// split fp32 -> (bf16 hi, bf16 lo)
__global__ void split_kernel(const float* __restrict__ x,
                             bf16* __restrict__ h, bf16* __restrict__ l, int n)
{
    int i = blockIdx.x * blockDim.x + threadIdx.x;
    if (i >= n) return;
    float v = x[i];
    bf16 hv = __float2bfloat16(v);
    h[i] = hv;
    l[i] = __float2bfloat16(v - __bfloat162float(hv));
}

// ---------------- cp.async helpers ----------------
__device__ __forceinline__ void cp16(void* dst, const void* src, bool pred) {
    unsigned int d = (unsigned int)__cvta_generic_to_shared(dst);
    int sz = pred ? 16 : 0;
    asm volatile("cp.async.cg.shared.global [%0], [%1], 16, %2;\n"
                 :: "r"(d), "l"(src), "r"(sz));
}
__device__ __forceinline__ void cp_commit() {
    asm volatile("cp.async.commit_group;\n" ::: "memory");
}
__device__ __forceinline__ void cp_wait1() {
    asm volatile("cp.async.wait_group 1;\n" ::: "memory");
}

// ================= bf16 split-WMMA GEMM, cp.async double-buffered =================
// Block tile 128x128, GBK=32 (two 16-substeps), 8 warps (4x2), warp tile 32x64.
// C = act(alpha * (Ah+Al)@(Bh+Bl) + bias + res); BT=false: B row-major [K,N];
// BT=true: C = ... A @ B^T with B row-major [N,K].
// mode: 0 = fp32 store, 1 = fp32 atomicAdd (split-K; bias/res only split 0),
//       2 = bf16 split store to Ch/Cl.
#define GBM 128
#define GBN 128
#define GBK 32
#define ALD 40            // padded ld for 128x32 tiles
#define BLD 136           // padded ld for 32x128 tiles (NN B)
#define STAGE_BYTES 40960
#define SMEM_TOTAL  (2 * STAGE_BYTES)

extern __shared__ unsigned char smem_dyn[];

template<bool BT>
__global__ __launch_bounds__(256)
void gemm_wmma(const bf16* __restrict__ Ah, const bf16* __restrict__ Al, int lda, long long sAz,
               const bf16* __restrict__ Bh, const bf16* __restrict__ Bl, int ldb, long long sBz,
               int Md, int Nd, int Kd, int nsplit, float alpha,
               const float* __restrict__ bias, const float* __restrict__ res, int ldres, int relu,
               int mode,
               float* __restrict__ C, int ldc, long long sCz,
               bf16* __restrict__ Ch, bf16* __restrict__ Cl)
{
    const int batch = blockIdx.z / nsplit;
    const int split = blockIdx.z % nsplit;
    Ah += (long long)batch * sAz;  Al += (long long)batch * sAz;
    Bh += (long long)batch * sBz;  Bl += (long long)batch * sBz;

    const int kLen = Kd / nsplit;
    const int kBeg = split * kLen;
    const int kEnd = kBeg + kLen;

    const int m0 = blockIdx.y * GBM;
    const int n0 = blockIdx.x * GBN;
    const int tid  = threadIdx.x;
    const int wid  = tid >> 5;
    const int lane = tid & 31;
    const int wm = wid >> 1;         // 0..3
    const int wn = wid & 1;          // 0..1

    using BLay = typename std::conditional<BT, wmma::col_major, wmma::row_major>::type;
    wmma::fragment<wmma::accumulator, 16, 16, 16, float> acc[2][4];
#pragma unroll
    for (int i = 0; i < 2; i++)
#pragma unroll
        for (int j = 0; j < 4; j++) wmma::fill_fragment(acc[i][j], 0.f);

    // ---- stage loader (cp.async) ----
    auto load_stage = [&](int s, int k0) {
        unsigned char* st = smem_dyn + s * STAGE_BYTES;
        bf16* ash = reinterpret_cast<bf16*>(st);
        bf16* asl = reinterpret_cast<bf16*>(st + 10240);
        bf16* bsh = reinterpret_cast<bf16*>(st + 20480);
        bf16* bsl = reinterpret_cast<bf16*>(st + 30720);
        // A tile: 128 rows x 32 k
#pragma unroll
        for (int it = 0; it < 2; it++) {
            int t = tid + it * 256;
            int row = t >> 2, kc = (t & 3) << 3;
            int gm = m0 + row, gk = k0 + kc;
            bool p = (gm < Md) && (gk < kEnd);
            long long off = (long long)gm * lda + gk;
            cp16(ash + row * ALD + kc, p ? (Ah + off) : Ah, p);
            cp16(asl + row * ALD + kc, p ? (Al + off) : Al, p);
        }
        if (BT) {
            // B^T tile: 128 n-rows x 32 k
#pragma unroll
            for (int it = 0; it < 2; it++) {
                int t = tid + it * 256;
                int row = t >> 2, kc = (t & 3) << 3;
                int gn = n0 + row, gk = k0 + kc;
                bool p = (gn < Nd) && (gk < kEnd);
                long long off = (long long)gn * ldb + gk;
                cp16(bsh + row * ALD + kc, p ? (Bh + off) : Bh, p);
                cp16(bsl + row * ALD + kc, p ? (Bl + off) : Bl, p);
            }
        } else {
            // B tile: 32 k-rows x 128 n
#pragma unroll
            for (int it = 0; it < 2; it++) {
                int t = tid + it * 256;
                int row = t >> 4, nc = (t & 15) << 3;
                int gk = k0 + row, gn = n0 + nc;
                bool p = (gk < kEnd) && (gn < Nd);
                long long off = (long long)gk * ldb + gn;
                cp16(bsh + row * BLD + nc, p ? (Bh + off) : Bh, p);
                cp16(bsl + row * BLD + nc, p ? (Bl + off) : Bl, p);
            }
        }
        cp_commit();
    };

    load_stage(0, kBeg);

    int s = 0;
    for (int k0 = kBeg; k0 < kEnd; k0 += GBK, s ^= 1) {
        if (k0 + GBK < kEnd) load_stage(s ^ 1, k0 + GBK);
        else cp_commit();
        cp_wait1();
        __syncthreads();

        unsigned char* st = smem_dyn + s * STAGE_BYTES;
        bf16* ash = reinterpret_cast<bf16*>(st);
        bf16* asl = reinterpret_cast<bf16*>(st + 10240);
        bf16* bsh = reinterpret_cast<bf16*>(st + 20480);
        bf16* bsl = reinterpret_cast<bf16*>(st + 30720);

#pragma unroll
        for (int ks = 0; ks < 2; ks++) {
            wmma::fragment<wmma::matrix_a, 16, 16, 16, bf16, wmma::row_major> ah[2], al[2];
#pragma unroll
            for (int mt = 0; mt < 2; mt++) {
                const bf16* ap = ash + (wm * 32 + mt * 16) * ALD + ks * 16;
                const bf16* lp = asl + (wm * 32 + mt * 16) * ALD + ks * 16;
                wmma::load_matrix_sync(ah[mt], ap, ALD);
                wmma::load_matrix_sync(al[mt], lp, ALD);
            }
#pragma unroll
            for (int nt = 0; nt < 4; nt++) {
                wmma::fragment<wmma::matrix_b, 16, 16, 16, bf16, BLay> bh, bl;
                if (BT) {
                    const bf16* bp = bsh + (wn * 64 + nt * 16) * ALD + ks * 16;
                    const bf16* qp = bsl + (wn * 64 + nt * 16) * ALD + ks * 16;
                    wmma::load_matrix_sync(bh, bp, ALD);
                    wmma::load_matrix_sync(bl, qp, ALD);
                } else {
                    const bf16* bp = bsh + (ks * 16) * BLD + wn * 64 + nt * 16;
                    const bf16* qp = bsl + (ks * 16) * BLD + wn * 64 + nt * 16;
                    wmma::load_matrix_sync(bh, bp, BLD);
                    wmma::load_matrix_sync(bl, qp, BLD);
                }
#pragma unroll
                for (int mt = 0; mt < 2; mt++) {
                    wmma::mma_sync(acc[mt][nt], ah[mt], bh, acc[mt][nt]);
                    wmma::mma_sync(acc[mt][nt], ah[mt], bl, acc[mt][nt]);
                    wmma::mma_sync(acc[mt][nt], al[mt], bh, acc[mt][nt]);
                }
            }
        }
        __syncthreads();
    }

    // ---- epilogue: stage each 16x16 frag through smem, apply fused ops ----
    float* patch = reinterpret_cast<float*>(smem_dyn) + wid * 256;
    const bool addx = (nsplit == 1) || (split == 0);
    C  += (long long)batch * sCz;

#pragma unroll
    for (int mt = 0; mt < 2; mt++) {
        int mbase = m0 + wm * 32 + mt * 16;
        if (mbase >= Md) continue;
#pragma unroll
        for (int nt = 0; nt < 4; nt++) {
            int nbase = n0 + wn * 64 + nt * 16;
            if (nbase >= Nd) continue;
            wmma::store_matrix_sync(patch, acc[mt][nt], 16, wmma::mem_row_major);
            __syncwarp();
#pragma unroll
            for (int j = 0; j < 8; j++) {
                int e = lane + j * 32;
                int m = mbase + (e >> 4);
                int n = nbase + (e & 15);
                float v = patch[e] * alpha;
                if (addx) {
                    if (bias) v += bias[n];
                    if (res)  v += res[(long long)m * ldres + n];
                    if (relu) v = fmaxf(v, 0.f);
                }
                long long co = (long long)m * ldc + n;
                if (mode == 0) {
                    C[co] = v;
                } else if (mode == 1) {
                    atomicAdd(&C[co], v);
                } else {
                    bf16 hv = __float2bfloat16(v);
                    Ch[co] = hv;
                    Cl[co] = __float2bfloat16(v - __bfloat162float(hv));
                }
            }
            __syncwarp();
        }
    }
}

// ---------------- softmax over rows (len LK); write split-bf16 probs ----------------
__global__ __launch_bounds__(256)
void softmax_kernel(const float* __restrict__ S, bf16* __restrict__ Ph, bf16* __restrict__ Pl)
{
    __shared__ float buf[LK];
    __shared__ float sred[32];
    const float* p = S + (size_t)blockIdx.x * LK;
    bf16* ph = Ph + (size_t)blockIdx.x * LK;
    bf16* pl = Pl + (size_t)blockIdx.x * LK;
    const int t = threadIdx.x;

    float mx = -1e30f;
    for (int i = t; i < LK / 4; i += 256) {
        float4 v = reinterpret_cast<const float4*>(p)[i];
        reinterpret_cast<float4*>(buf)[i] = v;
        mx = fmaxf(fmaxf(mx, fmaxf(v.x, v.y)), fmaxf(v.z, v.w));
    }
    mx = block_reduce_max(mx, sred);

    float sum = 0.f;
    for (int i = t; i < LK / 4; i += 256) {
        float4 v = reinterpret_cast<const float4*>(buf)[i];
        v.x = __expf(v.x - mx);
        v.y = __expf(v.y - mx);
        v.z = __expf(v.z - mx);
        v.w = __expf(v.w - mx);
        reinterpret_cast<float4*>(buf)[i] = v;
        sum += (v.x + v.y) + (v.z + v.w);
    }
    sum = block_reduce_sum(sum, sred);
    float inv = 1.f / sum;
    for (int i = t; i < LK / 4; i += 256) {
        float4 v = reinterpret_cast<const float4*>(buf)[i];
        float p0 = v.x * inv, p1 = v.y * inv, p2 = v.z * inv, p3 = v.w * inv;
        bf16 h0 = __float2bfloat16(p0), h1 = __float2bfloat16(p1);
        bf16 h2 = __float2bfloat16(p2), h3 = __float2bfloat16(p3);
        ushort4 hh, ll;
        hh.x = __bfloat16_as_ushort(h0); hh.y = __bfloat16_as_ushort(h1);
        hh.z = __bfloat16_as_ushort(h2); hh.w = __bfloat16_as_ushort(h3);
        ll.x = __bfloat16_as_ushort(__float2bfloat16(p0 - __bfloat162float(h0)));
        ll.y = __bfloat16_as_ushort(__float2bfloat16(p1 - __bfloat162float(h1)));
        ll.z = __bfloat16_as_ushort(__float2bfloat16(p2 - __bfloat162float(h2)));
        ll.w = __bfloat16_as_ushort(__float2bfloat16(p3 - __bfloat162float(h3)));
        reinterpret_cast<ushort4*>(ph)[i] = hh;
        reinterpret_cast<ushort4*>(pl)[i] = ll;
    }
}

// ---------------- column sum of probs (hi part only) -> attn_sum ----------------
__global__ void colsum_kernel(const bf16* __restrict__ Ph,
                              float* __restrict__ asum, int rows_per_chunk, int total_rows)
{
    int k = blockIdx.x * blockDim.x + threadIdx.x;
    if (k >= LK) return;
    int r0 = blockIdx.y * rows_per_chunk;
    int r1 = min(r0 + rows_per_chunk, total_rows);
    float s = 0.f;
    for (int r = r0; r < r1; r++) {
        s += __bfloat162float(Ph[(size_t)r * LK + k]);
    }
    atomicAdd(&asum[k], s);
}

// ---------------- layernorm over D=896 per row (optional split-bf16 output) ----------------
__global__ __launch_bounds__(224)
void layernorm_kernel(const float* __restrict__ X, const float* __restrict__ g,
                      const float* __restrict__ b, float* __restrict__ Y,
                      bf16* __restrict__ Yh, bf16* __restrict__ Yl)
{
    __shared__ float sred[32];
    const float* x = X + (size_t)blockIdx.x * Dm;
    const int t = threadIdx.x;

    float4 xv = *reinterpret_cast<const float4*>(x + t * 4);
    float s = (xv.x + xv.y) + (xv.z + xv.w);
    s = block_reduce_sum(s, sred);
    float mu = s * (1.0f / Dm);

    float d0 = xv.x - mu, d1 = xv.y - mu, d2 = xv.z - mu, d3 = xv.w - mu;
    float sq = (d0 * d0 + d1 * d1) + (d2 * d2 + d3 * d3);
    sq = block_reduce_sum(sq, sred);
    float inv = rsqrtf(sq * (1.0f / Dm) + 1e-12f);

    float4 gv = *reinterpret_cast<const float4*>(g + t * 4);
    float4 bv = *reinterpret_cast<const float4*>(b + t * 4);
    float4 ov;
    ov.x = d0 * inv * gv.x + bv.x;
    ov.y = d1 * inv * gv.y + bv.y;
    ov.z = d2 * inv * gv.z + bv.z;
    ov.w = d3 * inv * gv.w + bv.w;
    if (Y) *reinterpret_cast<float4*>(Y + (size_t)blockIdx.x * Dm + t * 4) = ov;
    if (Yh) {
        size_t base = (size_t)blockIdx.x * Dm + t * 4;
        bf16 h0 = __float2bfloat16(ov.x), h1 = __float2bfloat16(ov.y);
        bf16 h2 = __float2bfloat16(ov.z), h3 = __float2bfloat16(ov.w);
        ushort4 hh, ll;
        hh.x = __bfloat16_as_ushort(h0); hh.y = __bfloat16_as_ushort(h1);
        hh.z = __bfloat16_as_ushort(h2); hh.w = __bfloat16_as_ushort(h3);
        ll.x = __bfloat16_as_ushort(__float2bfloat16(ov.x - __bfloat162float(h0)));
        ll.y = __bfloat16_as_ushort(__float2bfloat16(ov.y - __bfloat162float(h1)));
        ll.z = __bfloat16_as_ushort(__float2bfloat16(ov.z - __bfloat162float(h2)));
        ll.w = __bfloat16_as_ushort(__float2bfloat16(ov.w - __bfloat162float(h3)));
        *reinterpret_cast<ushort4*>(Yh + base) = hh;
        *reinterpret_cast<ushort4*>(Yl + base) = ll;
    }
}

// ---------------- frame scores: mean over 196 per frame ----------------
__global__ void frame_kernel(const float* __restrict__ asum, float* __restrict__ out)
{
    __shared__ float red[256];
    int f = blockIdx.x;
    float s = 0.f;
    for (int i = threadIdx.x; i < Pp; i += blockDim.x) s += asum[f * Pp + i];
    red[threadIdx.x] = s;
    __syncthreads();
    for (int o = 128; o > 0; o >>= 1) {
        if (threadIdx.x < o) red[threadIdx.x] += red[threadIdx.x + o];
        __syncthreads();
    }
    if (threadIdx.x == 0) out[f] = red[0] * (1.0f / Pp);
}

// ---------------- host orchestration ----------------
extern "C" void kernel_launch(void* const* d_in, const int* in_sizes, int n_in,
                              void* d_out, int out_size)
{
    const float* img  = (const float*)d_in[0];
    const float* mem  = (const float*)d_in[1];
    const float* qW   = (const float*)d_in[2];
    const float* qb   = (const float*)d_in[3];
    const float* kW   = (const float*)d_in[4];
    const float* kb   = (const float*)d_in[5];
    const float* vW   = (const float*)d_in[6];
    const float* vb   = (const float*)d_in[7];
    const float* oW   = (const float*)d_in[8];
    const float* ob   = (const float*)d_in[9];
    const float* ln1g = (const float*)d_in[10];
    const float* ln1b = (const float*)d_in[11];
    const float* mW   = (const float*)d_in[12];
    const float* mb   = (const float*)d_in[13];
    const float* pW   = (const float*)d_in[14];
    const float* pb   = (const float*)d_in[15];
    const float* ln2g = (const float*)d_in[16];
    const float* ln2b = (const float*)d_in[17];
    float* out = (float*)d_out;

#define SYMF(name) ({ void* _p; cudaGetSymbolAddress(&_p, name); (float*)_p; })
#define SYMB(name) ({ void* _p; cudaGetSymbolAddress(&_p, name); (bf16*)_p; })

    float* Sp    = SYMF(g_S);
    bf16 *Php = SYMB(g_Ph), *Plp = SYMB(g_Pl);
    bf16 *memh = SYMB(g_memh), *meml = SYMB(g_meml);
    bf16 *imgh = SYMB(g_imgh), *imgl = SYMB(g_imgl);
    bf16 *qWh = SYMB(g_qWh), *qWl = SYMB(g_qWl);
    bf16 *kWh = SYMB(g_kWh), *kWl = SYMB(g_kWl);
    bf16 *vWh = SYMB(g_vWh), *vWl = SYMB(g_vWl);
    bf16 *oWh = SYMB(g_oWh), *oWl = SYMB(g_oWl);
    bf16 *mWh = SYMB(g_mWh), *mWl = SYMB(g_mWl);
    bf16 *pWh = SYMB(g_pWh), *pWl = SYMB(g_pWl);
    bf16 *Qh = SYMB(g_Qh), *Ql = SYMB(g_Ql);
    bf16 *Kh = SYMB(g_Kh), *Kl = SYMB(g_Kl);
    bf16 *Vh = SYMB(g_Vh), *Vl = SYMB(g_Vl);
    float* CTXp = SYMF(g_CTX);
    bf16 *CTXh = SYMB(g_CTXh), *CTXl = SYMB(g_CTXl);
    float* T1p = SYMF(g_T1);
    float* AOp = SYMF(g_AO);
    bf16 *AOh = SYMB(g_AOh), *AOl = SYMB(g_AOl);
    bf16 *HIDh = SYMB(g_HIDh), *HIDl = SYMB(g_HIDl);
    float* T2p = SYMF(g_T2);
    float* ASUMp = SYMF(g_ASUM);

    const float inv_sqrt_hd = 0.09449111825230681f;  // 1/sqrt(112)

    // allow 80KB dynamic smem on the GEMM kernels (idempotent host calls)
    cudaFuncSetAttribute(gemm_wmma<false>, cudaFuncAttributeMaxDynamicSharedMemorySize, SMEM_TOTAL);
    cudaFuncSetAttribute(gemm_wmma<true>,  cudaFuncAttributeMaxDynamicSharedMemorySize, SMEM_TOTAL);

    // ---- split inputs & weights to bf16 hi/lo ----
    auto split = [&](const float* x, bf16* h, bf16* l, int n) {
        split_kernel<<<(n + 255) / 256, 256>>>(x, h, l, n);
    };
    split(mem, memh, meml, LQ * Dm);
    split(img, imgh, imgl, LK * Dm);
    split(qW, qWh, qWl, Dm * Dm);
    split(kW, kWh, kWl, Dm * Dm);
    split(vW, vWh, vWl, Dm * Dm);
    split(oW, oWh, oWl, Dm * Dm);
    split(mW, mWh, mWl, Dm * D4);
    split(pW, pWh, pWl, D4 * Dm);

    // zero atomic-accumulated buffers
    zero_kernel<<<(LQ * Dm + 255) / 256, 256>>>(CTXp, LQ * Dm);
    zero_kernel<<<(LK + 255) / 256, 256>>>(ASUMp, LK);

    // ---- Q/K/V projections -> split bf16 (mode 2) ----
    gemm_wmma<false><<<dim3(7, 13, 1), 256, SMEM_TOTAL>>>(
        memh, meml, Dm, 0, qWh, qWl, Dm, 0,
        LQ, Dm, Dm, 1, 1.f, qb, nullptr, 0, 0, 2,
        nullptr, Dm, 0, Qh, Ql);
    gemm_wmma<false><<<dim3(7, 49, 1), 256, SMEM_TOTAL>>>(
        imgh, imgl, Dm, 0, kWh, kWl, Dm, 0,
        LK, Dm, Dm, 1, 1.f, kb, nullptr, 0, 0, 2,
        nullptr, Dm, 0, Kh, Kl);
    gemm_wmma<false><<<dim3(7, 49, 1), 256, SMEM_TOTAL>>>(
        imgh, imgl, Dm, 0, vWh, vWl, Dm, 0,
        LK, Dm, Dm, 1, 1.f, vb, nullptr, 0, 0, 2,
        nullptr, Dm, 0, Vh, Vl);

    // ---- scores[h] = Q_h @ K_h^T * (1/sqrt(HD)) -> fp32 S ----
    gemm_wmma<true><<<dim3(49, 13, Hh), 256, SMEM_TOTAL>>>(
        Qh, Ql, Dm, HDd, Kh, Kl, Dm, HDd,
        LQ, LK, HDd, 1, inv_sqrt_hd, nullptr, nullptr, 0, 0, 0,
        Sp, LK, (long long)LQ * LK, nullptr, nullptr);

    // ---- softmax -> split-bf16 probs ----
    softmax_kernel<<<Hh * LQ, 256>>>(Sp, Php, Plp);

    // ---- attn_sum (hi probs only; residual noise ~1e-5) ----
    colsum_kernel<<<dim3((LK + 255) / 256, 32), 256>>>(Php, ASUMp, (Hh * LQ) / 32, Hh * LQ);

    // ---- ctx[h] = probs[h] @ V_h  (split-K=4, fp32 atomics) ----
    gemm_wmma<false><<<dim3(1, 13, Hh * 4), 256, SMEM_TOTAL>>>(
        Php, Plp, LK, (long long)LQ * LK, Vh, Vl, Dm, HDd,
        LQ, HDd, LK, 4, 1.f, nullptr, nullptr, 0, 0, 1,
        CTXp, Dm, HDd, nullptr, nullptr);

    // split ctx for O projection
    split(CTXp, CTXh, CTXl, LQ * Dm);

    // ---- T1 = ctx @ oW + ob + mem ----
    gemm_wmma<false><<<dim3(7, 13, 1), 256, SMEM_TOTAL>>>(
        CTXh, CTXl, Dm, 0, oWh, oWl, Dm, 0,
        LQ, Dm, Dm, 1, 1.f, ob, mem, Dm, 0, 0,
        T1p, Dm, 0, nullptr, nullptr);

    // ---- attn_out = LN1(T1)  (fp32 + split bf16) ----
    layernorm_kernel<<<LQ, 224>>>(T1p, ln1g, ln1b, AOp, AOh, AOl);

    // ---- hidden = relu(attn_out @ mW + mb) -> split bf16 ----
    gemm_wmma<false><<<dim3(28, 13, 1), 256, SMEM_TOTAL>>>(
        AOh, AOl, Dm, 0, mWh, mWl, D4, 0,
        LQ, D4, Dm, 1, 1.f, mb, nullptr, 0, 1, 2,
        nullptr, D4, 0, HIDh, HIDl);

    // ---- T2 = hidden @ pW + pb + attn_out ----
    gemm_wmma<false><<<dim3(7, 13, 1), 256, SMEM_TOTAL>>>(
        HIDh, HIDl, D4, 0, pWh, pWl, Dm, 0,
        LQ, Dm, D4, 1, 1.f, pb, AOp, Dm, 0, 0,
        T2p, Dm, 0, nullptr, nullptr);

    // ---- out = LN2(T2) ----
    layernorm_kernel<<<LQ, 224>>>(T2p, ln2g, ln2b, out, nullptr, nullptr);

    // ---- frame scores ----
    frame_kernel<<<Ff, 256>>>(ASUMp, out + (size_t)LQ * Dm);
}

// round 15
// speedup vs baseline: 1.0031x; 1.0031x over previous
#include <cuda_runtime.h>
#include <cuda_bf16.h>
#include <mma.h>
#include <math.h>
#include <type_traits>

using namespace nvcuda;
typedef __nv_bfloat16 bf16;

// ---------------- problem constants ----------------
#define Dm   896
#define Hh   8
#define HDd  112
#define Pp   196
#define Ff   32
#define LQ   1568           // M * P
#define LK   6272           // F * P
#define D4   3584           // 4 * D

// ---------------- scratch (device globals; no allocs allowed) ----------------
__device__ __align__(256) float g_S  [(size_t)Hh * LQ * LK];   // fp32 scores (314 MB)
__device__ __align__(256) bf16  g_Ph [(size_t)Hh * LQ * LK];   // probs hi
__device__ __align__(256) bf16  g_Pl [(size_t)Hh * LQ * LK];   // probs lo

__device__ __align__(256) bf16 g_memh[LQ * Dm], g_meml[LQ * Dm];
__device__ __align__(256) bf16 g_imgh[LK * Dm], g_imgl[LK * Dm];
__device__ __align__(256) bf16 g_qWh[Dm * Dm], g_qWl[Dm * Dm];
__device__ __align__(256) bf16 g_kWh[Dm * Dm], g_kWl[Dm * Dm];
__device__ __align__(256) bf16 g_vWh[Dm * Dm], g_vWl[Dm * Dm];
__device__ __align__(256) bf16 g_oWh[Dm * Dm], g_oWl[Dm * Dm];
__device__ __align__(256) bf16 g_mWh[(size_t)Dm * D4], g_mWl[(size_t)Dm * D4];
__device__ __align__(256) bf16 g_pWh[(size_t)D4 * Dm], g_pWl[(size_t)D4 * Dm];

__device__ __align__(256) bf16 g_Qh[LQ * Dm], g_Ql[LQ * Dm];
__device__ __align__(256) bf16 g_Kh[LK * Dm], g_Kl[LK * Dm];
__device__ __align__(256) bf16 g_Vh[LK * Dm], g_Vl[LK * Dm];
__device__ __align__(256) float g_CTX[LQ * Dm];
__device__ __align__(256) bf16 g_CTXh[LQ * Dm], g_CTXl[LQ * Dm];
__device__ __align__(256) float g_T1[LQ * Dm];
__device__ __align__(256) float g_AO[LQ * Dm];
__device__ __align__(256) bf16 g_AOh[LQ * Dm], g_AOl[LQ * Dm];
__device__ __align__(256) bf16 g_HIDh[(size_t)LQ * D4], g_HIDl[(size_t)LQ * D4];
__device__ __align__(256) float g_T2[LQ * Dm];
__device__ __align__(256) float g_ASUM[LK];

// ---------------- reductions ----------------
__device__ __forceinline__ float warp_reduce_sum(float v) {
#pragma unroll
    for (int o = 16; o > 0; o >>= 1) v += __shfl_down_sync(0xffffffffu, v, o);
    return v;
}
__device__ __forceinline__ float warp_reduce_max(float v) {
#pragma unroll
    for (int o = 16; o > 0; o >>= 1) v = fmaxf(v, __shfl_down_sync(0xffffffffu, v, o));
    return v;
}
__device__ __forceinline__ float block_reduce_sum(float v, float* sred) {
    __syncthreads();
    v = warp_reduce_sum(v);
    if ((threadIdx.x & 31) == 0) sred[threadIdx.x >> 5] = v;
    __syncthreads();
    int nw = (blockDim.x + 31) >> 5;
    if (threadIdx.x < 32) {
        float x = (threadIdx.x < nw) ? sred[threadIdx.x] : 0.f;
        x = warp_reduce_sum(x);
        if (threadIdx.x == 0) sred[0] = x;
    }
    __syncthreads();
    return sred[0];
}
__device__ __forceinline__ float block_reduce_max(float v, float* sred) {
    __syncthreads();
    v = warp_reduce_max(v);
    if ((threadIdx.x & 31) == 0) sred[threadIdx.x >> 5] = v;
    __syncthreads();
    int nw = (blockDim.x + 31) >> 5;
    if (threadIdx.x < 32) {
        float x = (threadIdx.x < nw) ? sred[threadIdx.x] : -1e30f;
        x = warp_reduce_max(x);
        if (threadIdx.x == 0) sred[0] = x;
    }
    __syncthreads();
    return sred[0];
}

// ---------------- utility kernels ----------------
__global__ void zero_kernel(float* __restrict__ p, int n) {
    int i = blockIdx.x * blockDim.x + threadIdx.x;
    if (i < n) p[i] = 0.f;
}

// split fp32 -> (bf16 hi, bf16 lo)
__global__ void split_kernel(const float* __restrict__ x,
                             bf16* __restrict__ h, bf16* __restrict__ l, int n)
{
    int i = blockIdx.x * blockDim.x + threadIdx.x;
    if (i >= n) return;
    float v = x[i];
    bf16 hv = __float2bfloat16(v);
    h[i] = hv;
    l[i] = __float2bfloat16(v - __bfloat162float(hv));
}

// ---------------- cp.async helpers ----------------
__device__ __forceinline__ void cp16(void* dst, const void* src, bool pred) {
    unsigned int d = (unsigned int)__cvta_generic_to_shared(dst);
    int sz = pred ? 16 : 0;
    asm volatile("cp.async.cg.shared.global [%0], [%1], 16, %2;\n"
                 :: "r"(d), "l"(src), "r"(sz));
}
__device__ __forceinline__ void cp_commit() {
    asm volatile("cp.async.commit_group;\n" ::: "memory");
}
__device__ __forceinline__ void cp_wait1() {
    asm volatile("cp.async.wait_group 1;\n" ::: "memory");
}

// ================= bf16 split-WMMA GEMM, cp.async double-buffered =================
// Block tile 128x128, GBK=32 (two 16-substeps), 8 warps (4x2), warp tile 32x64.
// C = act(alpha * (Ah+Al)@(Bh+Bl) + bias + res); BT=false: B row-major [K,N];
// BT=true: C = ... A @ B^T with B row-major [N,K].
// mode: 0 = fp32 store, 1 = fp32 atomicAdd (split-K; bias/res only split 0),
//       2 = bf16 split store to Ch/Cl.
#define GBM 128
#define GBN 128
#define GBK 32
#define ALD 40            // padded ld for 128x32 tiles
#define BLD 136           // padded ld for 32x128 tiles (NN B)
#define STAGE_BYTES 40960
#define SMEM_TOTAL  (2 * STAGE_BYTES)

extern __shared__ unsigned char smem_dyn[];

template<bool BT>
__global__ __launch_bounds__(256)
void gemm_wmma(const bf16* __restrict__ Ah, const bf16* __restrict__ Al, int lda, long long sAz,
               const bf16* __restrict__ Bh, const bf16* __restrict__ Bl, int ldb, long long sBz,
               int Md, int Nd, int Kd, int nsplit, float alpha,
               const float* __restrict__ bias, const float* __restrict__ res, int ldres, int relu,
               int mode,
               float* __restrict__ C, int ldc, long long sCz,
               bf16* __restrict__ Ch, bf16* __restrict__ Cl)
{
    const int batch = blockIdx.z / nsplit;
    const int split = blockIdx.z % nsplit;
    Ah += (long long)batch * sAz;  Al += (long long)batch * sAz;
    Bh += (long long)batch * sBz;  Bl += (long long)batch * sBz;

    const int kLen = Kd / nsplit;
    const int kBeg = split * kLen;
    const int kEnd = kBeg + kLen;

    const int m0 = blockIdx.y * GBM;
    const int n0 = blockIdx.x * GBN;
    const int tid  = threadIdx.x;
    const int wid  = tid >> 5;
    const int lane = tid & 31;
    const int wm = wid >> 1;         // 0..3
    const int wn = wid & 1;          // 0..1

    using BLay = typename std::conditional<BT, wmma::col_major, wmma::row_major>::type;
    wmma::fragment<wmma::accumulator, 16, 16, 16, float> acc[2][4];
#pragma unroll
    for (int i = 0; i < 2; i++)
#pragma unroll
        for (int j = 0; j < 4; j++) wmma::fill_fragment(acc[i][j], 0.f);

    // ---- stage loader (cp.async) ----
    auto load_stage = [&](int s, int k0) {
        unsigned char* st = smem_dyn + s * STAGE_BYTES;
        bf16* ash = reinterpret_cast<bf16*>(st);
        bf16* asl = reinterpret_cast<bf16*>(st + 10240);
        bf16* bsh = reinterpret_cast<bf16*>(st + 20480);
        bf16* bsl = reinterpret_cast<bf16*>(st + 30720);
        // A tile: 128 rows x 32 k
#pragma unroll
        for (int it = 0; it < 2; it++) {
            int t = tid + it * 256;
            int row = t >> 2, kc = (t & 3) << 3;
            int gm = m0 + row, gk = k0 + kc;
            bool p = (gm < Md) && (gk < kEnd);
            long long off = (long long)gm * lda + gk;
            cp16(ash + row * ALD + kc, p ? (Ah + off) : Ah, p);
            cp16(asl + row * ALD + kc, p ? (Al + off) : Al, p);
        }
        if (BT) {
            // B^T tile: 128 n-rows x 32 k
#pragma unroll
            for (int it = 0; it < 2; it++) {
                int t = tid + it * 256;
                int row = t >> 2, kc = (t & 3) << 3;
                int gn = n0 + row, gk = k0 + kc;
                bool p = (gn < Nd) && (gk < kEnd);
                long long off = (long long)gn * ldb + gk;
                cp16(bsh + row * ALD + kc, p ? (Bh + off) : Bh, p);
                cp16(bsl + row * ALD + kc, p ? (Bl + off) : Bl, p);
            }
        } else {
            // B tile: 32 k-rows x 128 n
#pragma unroll
            for (int it = 0; it < 2; it++) {
                int t = tid + it * 256;
                int row = t >> 4, nc = (t & 15) << 3;
                int gk = k0 + row, gn = n0 + nc;
                bool p = (gk < kEnd) && (gn < Nd);
                long long off = (long long)gk * ldb + gn;
                cp16(bsh + row * BLD + nc, p ? (Bh + off) : Bh, p);
                cp16(bsl + row * BLD + nc, p ? (Bl + off) : Bl, p);
            }
        }
        cp_commit();
    };

    load_stage(0, kBeg);

    int s = 0;
    for (int k0 = kBeg; k0 < kEnd; k0 += GBK, s ^= 1) {
        if (k0 + GBK < kEnd) load_stage(s ^ 1, k0 + GBK);
        else cp_commit();
        cp_wait1();
        __syncthreads();

        unsigned char* st = smem_dyn + s * STAGE_BYTES;
        bf16* ash = reinterpret_cast<bf16*>(st);
        bf16* asl = reinterpret_cast<bf16*>(st + 10240);
        bf16* bsh = reinterpret_cast<bf16*>(st + 20480);
        bf16* bsl = reinterpret_cast<bf16*>(st + 30720);

#pragma unroll
        for (int ks = 0; ks < 2; ks++) {
            wmma::fragment<wmma::matrix_a, 16, 16, 16, bf16, wmma::row_major> ah[2], al[2];
#pragma unroll
            for (int mt = 0; mt < 2; mt++) {
                const bf16* ap = ash + (wm * 32 + mt * 16) * ALD + ks * 16;
                const bf16* lp = asl + (wm * 32 + mt * 16) * ALD + ks * 16;
                wmma::load_matrix_sync(ah[mt], ap, ALD);
                wmma::load_matrix_sync(al[mt], lp, ALD);
            }
#pragma unroll
            for (int nt = 0; nt < 4; nt++) {
                wmma::fragment<wmma::matrix_b, 16, 16, 16, bf16, BLay> bh, bl;
                if (BT) {
                    const bf16* bp = bsh + (wn * 64 + nt * 16) * ALD + ks * 16;
                    const bf16* qp = bsl + (wn * 64 + nt * 16) * ALD + ks * 16;
                    wmma::load_matrix_sync(bh, bp, ALD);
                    wmma::load_matrix_sync(bl, qp, ALD);
                } else {
                    const bf16* bp = bsh + (ks * 16) * BLD + wn * 64 + nt * 16;
                    const bf16* qp = bsl + (ks * 16) * BLD + wn * 64 + nt * 16;
                    wmma::load_matrix_sync(bh, bp, BLD);
                    wmma::load_matrix_sync(bl, qp, BLD);
                }
#pragma unroll
                for (int mt = 0; mt < 2; mt++) {
                    wmma::mma_sync(acc[mt][nt], ah[mt], bh, acc[mt][nt]);
                    wmma::mma_sync(acc[mt][nt], ah[mt], bl, acc[mt][nt]);
                    wmma::mma_sync(acc[mt][nt], al[mt], bh, acc[mt][nt]);
                }
            }
        }
        __syncthreads();
    }

    // ---- epilogue: stage each 16x16 frag through smem, apply fused ops ----
    float* patch = reinterpret_cast<float*>(smem_dyn) + wid * 256;
    const bool addx = (nsplit == 1) || (split == 0);
    C  += (long long)batch * sCz;

#pragma unroll
    for (int mt = 0; mt < 2; mt++) {
        int mbase = m0 + wm * 32 + mt * 16;
        if (mbase >= Md) continue;
#pragma unroll
        for (int nt = 0; nt < 4; nt++) {
            int nbase = n0 + wn * 64 + nt * 16;
            if (nbase >= Nd) continue;
            wmma::store_matrix_sync(patch, acc[mt][nt], 16, wmma::mem_row_major);
            __syncwarp();
#pragma unroll
            for (int j = 0; j < 8; j++) {
                int e = lane + j * 32;
                int m = mbase + (e >> 4);
                int n = nbase + (e & 15);
                float v = patch[e] * alpha;
                if (addx) {
                    if (bias) v += bias[n];
                    if (res)  v += res[(long long)m * ldres + n];
                    if (relu) v = fmaxf(v, 0.f);
                }
                long long co = (long long)m * ldc + n;
                if (mode == 0) {
                    C[co] = v;
                } else if (mode == 1) {
                    atomicAdd(&C[co], v);
                } else {
                    bf16 hv = __float2bfloat16(v);
                    Ch[co] = hv;
                    Cl[co] = __float2bfloat16(v - __bfloat162float(hv));
                }
            }
            __syncwarp();
        }
    }
}

// ---------------- softmax over rows (len LK); write split-bf16 probs ----------------
__global__ __launch_bounds__(256)
void softmax_kernel(const float* __restrict__ S, bf16* __restrict__ Ph, bf16* __restrict__ Pl)
{
    __shared__ float buf[LK];
    __shared__ float sred[32];
    const float* p = S + (size_t)blockIdx.x * LK;
    bf16* ph = Ph + (size_t)blockIdx.x * LK;
    bf16* pl = Pl + (size_t)blockIdx.x * LK;
    const int t = threadIdx.x;

    float mx = -1e30f;
    for (int i = t; i < LK / 4; i += 256) {
        float4 v = reinterpret_cast<const float4*>(p)[i];
        reinterpret_cast<float4*>(buf)[i] = v;
        mx = fmaxf(fmaxf(mx, fmaxf(v.x, v.y)), fmaxf(v.z, v.w));
    }
    mx = block_reduce_max(mx, sred);

    float sum = 0.f;
    for (int i = t; i < LK / 4; i += 256) {
        float4 v = reinterpret_cast<const float4*>(buf)[i];
        v.x = __expf(v.x - mx);
        v.y = __expf(v.y - mx);
        v.z = __expf(v.z - mx);
        v.w = __expf(v.w - mx);
        reinterpret_cast<float4*>(buf)[i] = v;
        sum += (v.x + v.y) + (v.z + v.w);
    }
    sum = block_reduce_sum(sum, sred);
    float inv = 1.f / sum;
    for (int i = t; i < LK / 4; i += 256) {
        float4 v = reinterpret_cast<const float4*>(buf)[i];
        float p0 = v.x * inv, p1 = v.y * inv, p2 = v.z * inv, p3 = v.w * inv;
        bf16 h0 = __float2bfloat16(p0), h1 = __float2bfloat16(p1);
        bf16 h2 = __float2bfloat16(p2), h3 = __float2bfloat16(p3);
        ushort4 hh, ll;
        hh.x = __bfloat16_as_ushort(h0); hh.y = __bfloat16_as_ushort(h1);
        hh.z = __bfloat16_as_ushort(h2); hh.w = __bfloat16_as_ushort(h3);
        ll.x = __bfloat16_as_ushort(__float2bfloat16(p0 - __bfloat162float(h0)));
        ll.y = __bfloat16_as_ushort(__float2bfloat16(p1 - __bfloat162float(h1)));
        ll.z = __bfloat16_as_ushort(__float2bfloat16(p2 - __bfloat162float(h2)));
        ll.w = __bfloat16_as_ushort(__float2bfloat16(p3 - __bfloat162float(h3)));
        reinterpret_cast<ushort4*>(ph)[i] = hh;
        reinterpret_cast<ushort4*>(pl)[i] = ll;
    }
}

// ---------------- column sum of probs (hi part only) -> attn_sum ----------------
__global__ void colsum_kernel(const bf16* __restrict__ Ph,
                              float* __restrict__ asum, int rows_per_chunk, int total_rows)
{
    int k = blockIdx.x * blockDim.x + threadIdx.x;
    if (k >= LK) return;
    int r0 = blockIdx.y * rows_per_chunk;
    int r1 = min(r0 + rows_per_chunk, total_rows);
    float s = 0.f;
    for (int r = r0; r < r1; r++) {
        s += __bfloat162float(Ph[(size_t)r * LK + k]);
    }
    atomicAdd(&asum[k], s);
}

// ---------------- layernorm over D=896 per row (optional split-bf16 output) ----------------
__global__ __launch_bounds__(224)
void layernorm_kernel(const float* __restrict__ X, const float* __restrict__ g,
                      const float* __restrict__ b, float* __restrict__ Y,
                      bf16* __restrict__ Yh, bf16* __restrict__ Yl)
{
    __shared__ float sred[32];
    const float* x = X + (size_t)blockIdx.x * Dm;
    const int t = threadIdx.x;

    float4 xv = *reinterpret_cast<const float4*>(x + t * 4);
    float s = (xv.x + xv.y) + (xv.z + xv.w);
    s = block_reduce_sum(s, sred);
    float mu = s * (1.0f / Dm);

    float d0 = xv.x - mu, d1 = xv.y - mu, d2 = xv.z - mu, d3 = xv.w - mu;
    float sq = (d0 * d0 + d1 * d1) + (d2 * d2 + d3 * d3);
    sq = block_reduce_sum(sq, sred);
    float inv = rsqrtf(sq * (1.0f / Dm) + 1e-12f);

    float4 gv = *reinterpret_cast<const float4*>(g + t * 4);
    float4 bv = *reinterpret_cast<const float4*>(b + t * 4);
    float4 ov;
    ov.x = d0 * inv * gv.x + bv.x;
    ov.y = d1 * inv * gv.y + bv.y;
    ov.z = d2 * inv * gv.z + bv.z;
    ov.w = d3 * inv * gv.w + bv.w;
    if (Y) *reinterpret_cast<float4*>(Y + (size_t)blockIdx.x * Dm + t * 4) = ov;
    if (Yh) {
        size_t base = (size_t)blockIdx.x * Dm + t * 4;
        bf16 h0 = __float2bfloat16(ov.x), h1 = __float2bfloat16(ov.y);
        bf16 h2 = __float2bfloat16(ov.z), h3 = __float2bfloat16(ov.w);
        ushort4 hh, ll;
        hh.x = __bfloat16_as_ushort(h0); hh.y = __bfloat16_as_ushort(h1);
        hh.z = __bfloat16_as_ushort(h2); hh.w = __bfloat16_as_ushort(h3);
        ll.x = __bfloat16_as_ushort(__float2bfloat16(ov.x - __bfloat162float(h0)));
        ll.y = __bfloat16_as_ushort(__float2bfloat16(ov.y - __bfloat162float(h1)));
        ll.z = __bfloat16_as_ushort(__float2bfloat16(ov.z - __bfloat162float(h2)));
        ll.w = __bfloat16_as_ushort(__float2bfloat16(ov.w - __bfloat162float(h3)));
        *reinterpret_cast<ushort4*>(Yh + base) = hh;
        *reinterpret_cast<ushort4*>(Yl + base) = ll;
    }
}

// ---------------- frame scores: mean over 196 per frame ----------------
__global__ void frame_kernel(const float* __restrict__ asum, float* __restrict__ out)
{
    __shared__ float red[256];
    int f = blockIdx.x;
    float s = 0.f;
    for (int i = threadIdx.x; i < Pp; i += blockDim.x) s += asum[f * Pp + i];
    red[threadIdx.x] = s;
    __syncthreads();
    for (int o = 128; o > 0; o >>= 1) {
        if (threadIdx.x < o) red[threadIdx.x] += red[threadIdx.x + o];
        __syncthreads();
    }
    if (threadIdx.x == 0) out[f] = red[0] * (1.0f / Pp);
}

// ---------------- host orchestration ----------------
extern "C" void kernel_launch(void* const* d_in, const int* in_sizes, int n_in,
                              void* d_out, int out_size)
{
    const float* img  = (const float*)d_in[0];
    const float* mem  = (const float*)d_in[1];
    const float* qW   = (const float*)d_in[2];
    const float* qb   = (const float*)d_in[3];
    const float* kW   = (const float*)d_in[4];
    const float* kb   = (const float*)d_in[5];
    const float* vW   = (const float*)d_in[6];
    const float* vb   = (const float*)d_in[7];
    const float* oW   = (const float*)d_in[8];
    const float* ob   = (const float*)d_in[9];
    const float* ln1g = (const float*)d_in[10];
    const float* ln1b = (const float*)d_in[11];
    const float* mW   = (const float*)d_in[12];
    const float* mb   = (const float*)d_in[13];
    const float* pW   = (const float*)d_in[14];
    const float* pb   = (const float*)d_in[15];
    const float* ln2g = (const float*)d_in[16];
    const float* ln2b = (const float*)d_in[17];
    float* out = (float*)d_out;

#define SYMF(name) ({ void* _p; cudaGetSymbolAddress(&_p, name); (float*)_p; })
#define SYMB(name) ({ void* _p; cudaGetSymbolAddress(&_p, name); (bf16*)_p; })

    float* Sp    = SYMF(g_S);
    bf16 *Php = SYMB(g_Ph), *Plp = SYMB(g_Pl);
    bf16 *memh = SYMB(g_memh), *meml = SYMB(g_meml);
    bf16 *imgh = SYMB(g_imgh), *imgl = SYMB(g_imgl);
    bf16 *qWh = SYMB(g_qWh), *qWl = SYMB(g_qWl);
    bf16 *kWh = SYMB(g_kWh), *kWl = SYMB(g_kWl);
    bf16 *vWh = SYMB(g_vWh), *vWl = SYMB(g_vWl);
    bf16 *oWh = SYMB(g_oWh), *oWl = SYMB(g_oWl);
    bf16 *mWh = SYMB(g_mWh), *mWl = SYMB(g_mWl);
    bf16 *pWh = SYMB(g_pWh), *pWl = SYMB(g_pWl);
    bf16 *Qh = SYMB(g_Qh), *Ql = SYMB(g_Ql);
    bf16 *Kh = SYMB(g_Kh), *Kl = SYMB(g_Kl);
    bf16 *Vh = SYMB(g_Vh), *Vl = SYMB(g_Vl);
    float* CTXp = SYMF(g_CTX);
    bf16 *CTXh = SYMB(g_CTXh), *CTXl = SYMB(g_CTXl);
    float* T1p = SYMF(g_T1);
    float* AOp = SYMF(g_AO);
    bf16 *AOh = SYMB(g_AOh), *AOl = SYMB(g_AOl);
    bf16 *HIDh = SYMB(g_HIDh), *HIDl = SYMB(g_HIDl);
    float* T2p = SYMF(g_T2);
    float* ASUMp = SYMF(g_ASUM);

    const float inv_sqrt_hd = 0.09449111825230681f;  // 1/sqrt(112)

    // allow 80KB dynamic smem on the GEMM kernels (idempotent host calls)
    cudaFuncSetAttribute(gemm_wmma<false>, cudaFuncAttributeMaxDynamicSharedMemorySize, SMEM_TOTAL);
    cudaFuncSetAttribute(gemm_wmma<true>,  cudaFuncAttributeMaxDynamicSharedMemorySize, SMEM_TOTAL);

    // ---- split inputs & weights to bf16 hi/lo ----
    auto split = [&](const float* x, bf16* h, bf16* l, int n) {
        split_kernel<<<(n + 255) / 256, 256>>>(x, h, l, n);
    };
    split(mem, memh, meml, LQ * Dm);
    split(img, imgh, imgl, LK * Dm);
    split(qW, qWh, qWl, Dm * Dm);
    split(kW, kWh, kWl, Dm * Dm);
    split(vW, vWh, vWl, Dm * Dm);
    split(oW, oWh, oWl, Dm * Dm);
    split(mW, mWh, mWl, Dm * D4);
    split(pW, pWh, pWl, D4 * Dm);

    // zero atomic-accumulated buffers
    zero_kernel<<<(LQ * Dm + 255) / 256, 256>>>(CTXp, LQ * Dm);
    zero_kernel<<<(LK + 255) / 256, 256>>>(ASUMp, LK);

    // ---- Q/K/V projections -> split bf16 (mode 2) ----
    gemm_wmma<false><<<dim3(7, 13, 1), 256, SMEM_TOTAL>>>(
        memh, meml, Dm, 0, qWh, qWl, Dm, 0,
        LQ, Dm, Dm, 1, 1.f, qb, nullptr, 0, 0, 2,
        nullptr, Dm, 0, Qh, Ql);
    gemm_wmma<false><<<dim3(7, 49, 1), 256, SMEM_TOTAL>>>(
        imgh, imgl, Dm, 0, kWh, kWl, Dm, 0,
        LK, Dm, Dm, 1, 1.f, kb, nullptr, 0, 0, 2,
        nullptr, Dm, 0, Kh, Kl);
    gemm_wmma<false><<<dim3(7, 49, 1), 256, SMEM_TOTAL>>>(
        imgh, imgl, Dm, 0, vWh, vWl, Dm, 0,
        LK, Dm, Dm, 1, 1.f, vb, nullptr, 0, 0, 2,
        nullptr, Dm, 0, Vh, Vl);

    // ---- scores[h] = Q_h @ K_h^T * (1/sqrt(HD)) -> fp32 S ----
    gemm_wmma<true><<<dim3(49, 13, Hh), 256, SMEM_TOTAL>>>(
        Qh, Ql, Dm, HDd, Kh, Kl, Dm, HDd,
        LQ, LK, HDd, 1, inv_sqrt_hd, nullptr, nullptr, 0, 0, 0,
        Sp, LK, (long long)LQ * LK, nullptr, nullptr);

    // ---- softmax -> split-bf16 probs ----
    softmax_kernel<<<Hh * LQ, 256>>>(Sp, Php, Plp);

    // ---- attn_sum (hi probs only; residual noise ~1e-5) ----
    colsum_kernel<<<dim3((LK + 255) / 256, 32), 256>>>(Php, ASUMp, (Hh * LQ) / 32, Hh * LQ);

    // ---- ctx[h] = probs[h] @ V_h  (split-K=4, fp32 atomics) ----
    gemm_wmma<false><<<dim3(1, 13, Hh * 4), 256, SMEM_TOTAL>>>(
        Php, Plp, LK, (long long)LQ * LK, Vh, Vl, Dm, HDd,
        LQ, HDd, LK, 4, 1.f, nullptr, nullptr, 0, 0, 1,
        CTXp, Dm, HDd, nullptr, nullptr);

    // split ctx for O projection
    split(CTXp, CTXh, CTXl, LQ * Dm);

    // ---- T1 = ctx @ oW + ob + mem ----
    gemm_wmma<false><<<dim3(7, 13, 1), 256, SMEM_TOTAL>>>(
        CTXh, CTXl, Dm, 0, oWh, oWl, Dm, 0,
        LQ, Dm, Dm, 1, 1.f, ob, mem, Dm, 0, 0,
        T1p, Dm, 0, nullptr, nullptr);

    // ---- attn_out = LN1(T1)  (fp32 + split bf16) ----
    layernorm_kernel<<<LQ, 224>>>(T1p, ln1g, ln1b, AOp, AOh, AOl);

    // ---- hidden = relu(attn_out @ mW + mb) -> split bf16 ----
    gemm_wmma<false><<<dim3(28, 13, 1), 256, SMEM_TOTAL>>>(
        AOh, AOl, Dm, 0, mWh, mWl, D4, 0,
        LQ, D4, Dm, 1, 1.f, mb, nullptr, 0, 1, 2,
        nullptr, D4, 0, HIDh, HIDl);

    // ---- T2 = hidden @ pW + pb + attn_out ----
    gemm_wmma<false><<<dim3(7, 13, 1), 256, SMEM_TOTAL>>>(
        HIDh, HIDl, D4, 0, pWh, pWl, Dm, 0,
        LQ, Dm, D4, 1, 1.f, pb, AOp, Dm, 0, 0,
        T2p, Dm, 0, nullptr, nullptr);

    // ---- out = LN2(T2) ----
    layernorm_kernel<<<LQ, 224>>>(T2p, ln2g, ln2b, out, nullptr, nullptr);

    // ---- frame scores ----
    frame_kernel<<<Ff, 256>>>(ASUMp, out + (size_t)LQ * Dm);
}